// round 15
// baseline (speedup 1.0000x reference)
#include <cuda_runtime.h>
#include <cuda_fp16.h>
#include <cstdint>

// ---------------- problem constants ----------------
#define N_TOK    2048
#define D_DIM    64
#define N_BATCH  32
#define BM       128                 // q-rows per CTA (8 warps x 16 rows)
#define BN       64                  // keys per tile
#define NTILES   (N_TOK / BN)        // 32
#define NTHREADS 256
#define EXP2_SCALE 0.18033688011112042f   // log2(e)/8
#define EXP2_SHIFT (-10.0f)  // constant log2 shift; cancels in O = sum(p v)/sum(p)

// smem layout (bytes). 128B rows, XOR-swizzled 16B chunks.
// K double buffer: compute reads buf[kt&1], cp.async fills buf[(kt+1)&1].
#define OFF_K0 0        // 64 x 64 f16 = 8 KB
#define OFF_K1 8192
#define OFF_QH 16384    // 128 x 64 f16 = 16 KB
#define OFF_QL 32768
#define SMEM_BYTES 49152

// chunk swizzle: physical 16B-chunk = c ^ (row & 7)
#define SWZ_ADDR(base, row, c) ((base) + (uint32_t)(row) * 128u + ((uint32_t)((c) ^ ((row) & 7)) * 16u))

// ---------------- static device scratch ----------------
__device__ __half  g_Xh[(size_t)N_BATCH * N_TOK * D_DIM];   // 8 MB
__device__ __half  g_Xl[(size_t)N_BATCH * N_TOK * D_DIM];   // 8 MB (Q lo only)
__device__ uint32_t g_adjm[N_TOK * (N_TOK / 32)];           // 512 KB

// ---------------- helpers ----------------
__device__ __forceinline__ uint32_t smem_u32(const void* p) {
    uint32_t a;
    asm("{ .reg .u64 t; cvta.to.shared.u64 t, %1; cvt.u32.u64 %0, t; }" : "=r"(a) : "l"(p));
    return a;
}
__device__ __forceinline__ float ex2f(float x) {
    float r; asm("ex2.approx.f32 %0, %1;" : "=f"(r) : "f"(x)); return r;
}
__device__ __forceinline__ void ldm4(uint32_t r[4], uint32_t addr) {
    asm volatile("ldmatrix.sync.aligned.m8n8.x4.shared.b16 {%0,%1,%2,%3}, [%4];"
                 : "=r"(r[0]), "=r"(r[1]), "=r"(r[2]), "=r"(r[3]) : "r"(addr));
}
__device__ __forceinline__ void ldm4t(uint32_t r[4], uint32_t addr) {
    asm volatile("ldmatrix.sync.aligned.m8n8.x4.trans.shared.b16 {%0,%1,%2,%3}, [%4];"
                 : "=r"(r[0]), "=r"(r[1]), "=r"(r[2]), "=r"(r[3]) : "r"(addr));
}
__device__ __forceinline__ void mma16816(float d[4], const uint32_t a[4],
                                         uint32_t b0, uint32_t b1) {
    asm volatile(
        "mma.sync.aligned.m16n8k16.row.col.f32.f16.f16.f32 "
        "{%0,%1,%2,%3}, {%4,%5,%6,%7}, {%8,%9}, {%0,%1,%2,%3};"
        : "+f"(d[0]), "+f"(d[1]), "+f"(d[2]), "+f"(d[3])
        : "r"(a[0]), "r"(a[1]), "r"(a[2]), "r"(a[3]), "r"(b0), "r"(b1));
}
__device__ __forceinline__ uint32_t pack_f16(float lo, float hi) {
    uint32_t r;  // first PTX source -> upper half
    asm("cvt.rn.f16x2.f32 %0, %1, %2;" : "=r"(r) : "f"(hi), "f"(lo));
    return r;
}
__device__ __forceinline__ void cp_async16(uint32_t smem_addr, const void* gptr) {
    asm volatile("cp.async.cg.shared.global [%0], [%1], 16;"
                 :: "r"(smem_addr), "l"(gptr) : "memory");
}
__device__ __forceinline__ void cp_async_commit() {
    asm volatile("cp.async.commit_group;" ::: "memory");
}
__device__ __forceinline__ void cp_async_wait0() {
    asm volatile("cp.async.wait_group 0;" ::: "memory");
}
// split two floats into packed f16 hi + f16 lo words (pre-pass only)
__device__ __forceinline__ void split2(float x, float y, uint32_t& hw, uint32_t& lw) {
    __half2 h2 = __floats2half2_rn(x, y);
    float2 f2 = __half22float2(h2);
    __half2 l2 = __floats2half2_rn(x - f2.x, y - f2.y);
    hw = *reinterpret_cast<uint32_t*>(&h2);
    lw = *reinterpret_cast<uint32_t*>(&l2);
}

// ---------------- pre-pass 1: split X into f16 hi/lo ----------------
__global__ void split_kernel(const float* __restrict__ X) {
    size_t i = (size_t)blockIdx.x * blockDim.x + threadIdx.x;   // one float4
    float4 v = reinterpret_cast<const float4*>(X)[i];
    uint32_t h01, l01, h23, l23;
    split2(v.x, v.y, h01, l01);
    split2(v.z, v.w, h23, l23);
    reinterpret_cast<uint2*>(g_Xh)[i] = make_uint2(h01, h23);
    reinterpret_cast<uint2*>(g_Xl)[i] = make_uint2(l01, l23);
}

// ---------------- pre-pass 2: bit-pack adjacency ----------------
__global__ void adj_pack_kernel(const int* __restrict__ adj) {
    int w = blockIdx.x * blockDim.x + threadIdx.x;   // word index
    const int4* p = reinterpret_cast<const int4*>(adj) + (size_t)w * 8;
    uint32_t m = 0;
    #pragma unroll
    for (int i = 0; i < 8; ++i) {
        int4 v = p[i];
        m |= (v.x > 0 ? 1u : 0u) << (i * 4 + 0);
        m |= (v.y > 0 ? 1u : 0u) << (i * 4 + 1);
        m |= (v.z > 0 ? 1u : 0u) << (i * 4 + 2);
        m |= (v.w > 0 ? 1u : 0u) << (i * 4 + 3);
    }
    g_adjm[w] = m;
}

// ---------------- main flash kernel ----------------
__global__ __launch_bounds__(NTHREADS, 2)
void gat_mma_kernel(float* __restrict__ out)
{
    extern __shared__ char smem[];
    const uint32_t sb = smem_u32(smem);

    const int tid  = threadIdx.x;
    const int wid  = tid >> 5;
    const int lane = tid & 31;

    const int batch = blockIdx.x >> 4;          // 32 batches x 16 mtiles
    const int mtile = blockIdx.x & 15;
    const int row0  = mtile * BM;
    const size_t xb = (size_t)batch * N_TOK * D_DIM;

    // ---- stage Q (hi+lo) into smem, swizzled ----
    #pragma unroll
    for (int it = 0; it < 4; ++it) {
        int c   = tid + it * 256;               // 0..1023 chunks
        int row = c >> 3, cd = c & 7;
        uint32_t dst = SWZ_ADDR(0u, row, cd);
        *reinterpret_cast<uint4*>(smem + OFF_QH + dst) =
            *reinterpret_cast<const uint4*>(g_Xh + xb + (size_t)(row0 + row) * 64 + cd * 8);
        *reinterpret_cast<uint4*>(smem + OFF_QL + dst) =
            *reinterpret_cast<const uint4*>(g_Xl + xb + (size_t)(row0 + row) * 64 + cd * 8);
    }

    // ---- K tile 0 preload via cp.async (key = tid>>2, chunks (tid&3)*2, +1) ----
    const int pk_key = tid >> 2;
    const int pk_cd  = (tid & 3) * 2;
    const uint32_t kst_dst0 = SWZ_ADDR(0u, pk_key, pk_cd);
    const uint32_t kst_dst1 = SWZ_ADDR(0u, pk_key, pk_cd + 1);
    {
        const size_t src = xb + (size_t)pk_key * 64 + pk_cd * 8;
        cp_async16(sb + OFF_K0 + kst_dst0, g_Xh + src);
        cp_async16(sb + OFF_K0 + kst_dst1, g_Xh + src + 8);
        cp_async_commit();
    }

    // per-warp fragment state
    float O[8][4];
    #pragma unroll
    for (int t = 0; t < 8; ++t)
        #pragma unroll
        for (int j = 0; j < 4; ++j) O[t][j] = 0.0f;
    float lA = 0.0f, lB = 0.0f;

    const int rowA = row0 + wid * 16 + (lane >> 2);   // global q-row of d0/d1
    const int qrow   = wid * 16 + (lane & 7) + ((lane >> 3) & 1) * 8;
    const int brow_b = ((lane >> 4) & 1) * 8 + (lane & 7);
    const int bchk_b = (lane >> 3) & 1;
    const int vrow_b = ((lane >> 3) & 1) * 8 + (lane & 7);

    cp_async_wait0();
    __syncthreads();   // Q smem + K tile 0 visible

    // ---- hoist Q fragments into registers (invariant across key tiles) ----
    uint32_t qh[4][4], ql[4][4];
    #pragma unroll
    for (int kc = 0; kc < 4; ++kc) {
        const int qchunk = kc * 2 + (lane >> 4);
        ldm4(qh[kc], sb + OFF_QH + SWZ_ADDR(0u, qrow, qchunk));
        ldm4(ql[kc], sb + OFF_QL + SWZ_ADDR(0u, qrow, qchunk));
    }

    for (int kt = 0; kt < NTILES; ++kt) {
        const uint32_t kbuf  = (kt & 1) ? OFF_K1 : OFF_K0;
        const uint32_t knext = (kt & 1) ? OFF_K0 : OFF_K1;

        // async prefetch of K(kt+1) into the idle buffer (overlaps compute)
        if (kt + 1 < NTILES) {
            const size_t src = xb + (size_t)((kt + 1) * BN + pk_key) * 64 + pk_cd * 8;
            cp_async16(sb + knext + kst_dst0, g_Xh + src);
            cp_async16(sb + knext + kst_dst1, g_Xh + src + 8);
            cp_async_commit();
        }

        // adjacency bits for my two rows, this tile's 64 keys
        uint2 mwA = *reinterpret_cast<const uint2*>(&g_adjm[(size_t)rowA * 64 + kt * 2]);
        uint2 mwB = *reinterpret_cast<const uint2*>(&g_adjm[(size_t)(rowA + 8) * 64 + kt * 2]);
        const uint64_t maskA = (uint64_t)mwA.x | ((uint64_t)mwA.y << 32);
        const uint64_t maskB = (uint64_t)mwB.x | ((uint64_t)mwB.y << 32);

        // ---- GEMM1: S = (Qh + Ql) * K^T  (2 passes, Q from registers) ----
        float S[8][4];
        #pragma unroll
        for (int t = 0; t < 8; ++t)
            #pragma unroll
            for (int j = 0; j < 4; ++j) S[t][j] = 0.0f;

        #pragma unroll
        for (int kc = 0; kc < 4; ++kc) {
            #pragma unroll
            for (int g = 0; g < 4; ++g) {
                const int brow = g * 16 + brow_b;
                const int bchk = kc * 2 + bchk_b;
                uint32_t b[4];
                ldm4(b, sb + kbuf + SWZ_ADDR(0u, brow, bchk));
                mma16816(S[2*g],   qh[kc], b[0], b[1]);
                mma16816(S[2*g+1], qh[kc], b[2], b[3]);
                mma16816(S[2*g],   ql[kc], b[0], b[1]);
                mma16816(S[2*g+1], ql[kc], b[2], b[3]);
            }
        }

        // ---- mask + shifted exp; pack P to f16 A-fragments directly ----
        uint32_t P[8][2];
        #pragma unroll
        for (int nt = 0; nt < 8; ++nt) {
            const int bit = nt * 8 + (lane & 3) * 2;
            float p0 = ((maskA >> bit) & 1ull)
                       ? ex2f(fmaf(S[nt][0], EXP2_SCALE, EXP2_SHIFT)) : 0.0f;
            float p1 = ((maskA >> (bit + 1)) & 1ull)
                       ? ex2f(fmaf(S[nt][1], EXP2_SCALE, EXP2_SHIFT)) : 0.0f;
            float p2 = ((maskB >> bit) & 1ull)
                       ? ex2f(fmaf(S[nt][2], EXP2_SCALE, EXP2_SHIFT)) : 0.0f;
            float p3 = ((maskB >> (bit + 1)) & 1ull)
                       ? ex2f(fmaf(S[nt][3], EXP2_SCALE, EXP2_SHIFT)) : 0.0f;
            lA += p0 + p1;
            lB += p2 + p3;
            P[nt][0] = pack_f16(p0, p1);
            P[nt][1] = pack_f16(p2, p3);
        }

        // ---- GEMM2: O += P * V  (single pass; V = K buffer via trans) ----
        #pragma unroll
        for (int u = 0; u < 4; ++u) {
            uint32_t a[4] = { P[2*u][0], P[2*u][1], P[2*u+1][0], P[2*u+1][1] };
            const int vrow = u * 16 + vrow_b;
            #pragma unroll
            for (int dd = 0; dd < 4; ++dd) {
                const int vchk = dd * 2 + (lane >> 4);
                uint32_t v[4];
                ldm4t(v, sb + kbuf + SWZ_ADDR(0u, vrow, vchk));
                mma16816(O[2*dd],   a, v[0], v[1]);
                mma16816(O[2*dd+1], a, v[2], v[3]);
            }
        }

        // drain the prefetch and publish buffer swap
        if (kt + 1 < NTILES) {
            cp_async_wait0();
            __syncthreads();
        }
    }

    // ---- epilogue: reduce l over quad, normalize, store ----
    lA += __shfl_xor_sync(0xffffffffu, lA, 1);
    lA += __shfl_xor_sync(0xffffffffu, lA, 2);
    lB += __shfl_xor_sync(0xffffffffu, lB, 1);
    lB += __shfl_xor_sync(0xffffffffu, lB, 2);
    const float invA = 1.0f / lA;
    const float invB = 1.0f / lB;

    float* poA = out + ((size_t)batch * N_TOK + rowA) * 64 + (lane & 3) * 2;
    float* poB = poA + 8 * 64;
    #pragma unroll
    for (int dt = 0; dt < 8; ++dt) {
        *reinterpret_cast<float2*>(poA + dt * 8) =
            make_float2(O[dt][0] * invA, O[dt][1] * invA);
        *reinterpret_cast<float2*>(poB + dt * 8) =
            make_float2(O[dt][2] * invB, O[dt][3] * invB);
    }
}

extern "C" void kernel_launch(void* const* d_in, const int* in_sizes, int n_in,
                              void* d_out, int out_size)
{
    const float* X   = (const float*)d_in[0];  // [32,2048,64] fp32
    const int*   adj = (const int*)d_in[1];    // [2048,2048] int32
    float*       out = (float*)d_out;

    split_kernel<<<(N_BATCH * N_TOK * D_DIM / 4) / 256, 256>>>(X);
    adj_pack_kernel<<<(N_TOK * (N_TOK / 32)) / 256, 256>>>(adj);

    cudaFuncSetAttribute(gat_mma_kernel,
                         cudaFuncAttributeMaxDynamicSharedMemorySize, SMEM_BYTES);
    gat_mma_kernel<<<N_BATCH * (N_TOK / BM), NTHREADS, SMEM_BYTES>>>(out);
}

// round 17
// speedup vs baseline: 1.1599x; 1.1599x over previous
#include <cuda_runtime.h>
#include <cuda_fp16.h>
#include <cstdint>

// ---------------- problem constants ----------------
#define N_TOK    2048
#define D_DIM    64
#define N_BATCH  32
#define BM       128                 // q-rows per CTA (8 warps x 16 rows)
#define BN       64                  // keys per tile
#define NTILES   (N_TOK / BN)        // 32
#define NTHREADS 256
#define EXP2_SCALE 0.18033688011112042f   // log2(e)/8
#define EXP2_SHIFT (-10.0f)  // constant log2 shift; cancels in O = sum(p v)/sum(p)

// smem layout (bytes). 128B rows, XOR-swizzled 16B chunks.
// K double buffer: compute reads buf[kt&1], cp.async fills buf[(kt+1)&1].
#define OFF_K0 0        // 64 x 64 f16 = 8 KB
#define OFF_K1 8192
#define OFF_QH 16384    // 128 x 64 f16 = 16 KB
#define SMEM_BYTES 32768

// chunk swizzle: physical 16B-chunk = c ^ (row & 7)
#define SWZ_ADDR(base, row, c) ((base) + (uint32_t)(row) * 128u + ((uint32_t)((c) ^ ((row) & 7)) * 16u))

// ---------------- static device scratch ----------------
__device__ __half  g_Xh[(size_t)N_BATCH * N_TOK * D_DIM];   // 8 MB
__device__ uint32_t g_adjm[N_TOK * (N_TOK / 32)];           // 512 KB

// ---------------- helpers ----------------
__device__ __forceinline__ uint32_t smem_u32(const void* p) {
    uint32_t a;
    asm("{ .reg .u64 t; cvta.to.shared.u64 t, %1; cvt.u32.u64 %0, t; }" : "=r"(a) : "l"(p));
    return a;
}
__device__ __forceinline__ float ex2f(float x) {
    float r; asm("ex2.approx.f32 %0, %1;" : "=f"(r) : "f"(x)); return r;
}
__device__ __forceinline__ void ldm4(uint32_t r[4], uint32_t addr) {
    asm volatile("ldmatrix.sync.aligned.m8n8.x4.shared.b16 {%0,%1,%2,%3}, [%4];"
                 : "=r"(r[0]), "=r"(r[1]), "=r"(r[2]), "=r"(r[3]) : "r"(addr));
}
__device__ __forceinline__ void ldm4t(uint32_t r[4], uint32_t addr) {
    asm volatile("ldmatrix.sync.aligned.m8n8.x4.trans.shared.b16 {%0,%1,%2,%3}, [%4];"
                 : "=r"(r[0]), "=r"(r[1]), "=r"(r[2]), "=r"(r[3]) : "r"(addr));
}
__device__ __forceinline__ void mma16816(float d[4], const uint32_t a[4],
                                         uint32_t b0, uint32_t b1) {
    asm volatile(
        "mma.sync.aligned.m16n8k16.row.col.f32.f16.f16.f32 "
        "{%0,%1,%2,%3}, {%4,%5,%6,%7}, {%8,%9}, {%0,%1,%2,%3};"
        : "+f"(d[0]), "+f"(d[1]), "+f"(d[2]), "+f"(d[3])
        : "r"(a[0]), "r"(a[1]), "r"(a[2]), "r"(a[3]), "r"(b0), "r"(b1));
}
__device__ __forceinline__ uint32_t pack_f16(float lo, float hi) {
    uint32_t r;  // first PTX source -> upper half
    asm("cvt.rn.f16x2.f32 %0, %1, %2;" : "=r"(r) : "f"(hi), "f"(lo));
    return r;
}
__device__ __forceinline__ void cp_async16(uint32_t smem_addr, const void* gptr) {
    asm volatile("cp.async.cg.shared.global [%0], [%1], 16;"
                 :: "r"(smem_addr), "l"(gptr) : "memory");
}
__device__ __forceinline__ void cp_async_commit() {
    asm volatile("cp.async.commit_group;" ::: "memory");
}
__device__ __forceinline__ void cp_async_wait0() {
    asm volatile("cp.async.wait_group 0;" ::: "memory");
}

// ---------------- pre-pass 1: convert X to f16 ----------------
__global__ void convert_kernel(const float* __restrict__ X) {
    size_t i = (size_t)blockIdx.x * blockDim.x + threadIdx.x;   // one float4
    float4 v = reinterpret_cast<const float4*>(X)[i];
    __half2 h01 = __floats2half2_rn(v.x, v.y);
    __half2 h23 = __floats2half2_rn(v.z, v.w);
    reinterpret_cast<uint2*>(g_Xh)[i] =
        make_uint2(*reinterpret_cast<uint32_t*>(&h01),
                   *reinterpret_cast<uint32_t*>(&h23));
}

// ---------------- pre-pass 2: bit-pack adjacency ----------------
__global__ void adj_pack_kernel(const int* __restrict__ adj) {
    int w = blockIdx.x * blockDim.x + threadIdx.x;   // word index
    const int4* p = reinterpret_cast<const int4*>(adj) + (size_t)w * 8;
    uint32_t m = 0;
    #pragma unroll
    for (int i = 0; i < 8; ++i) {
        int4 v = p[i];
        m |= (v.x > 0 ? 1u : 0u) << (i * 4 + 0);
        m |= (v.y > 0 ? 1u : 0u) << (i * 4 + 1);
        m |= (v.z > 0 ? 1u : 0u) << (i * 4 + 2);
        m |= (v.w > 0 ? 1u : 0u) << (i * 4 + 3);
    }
    g_adjm[w] = m;
}

// ---------------- main flash kernel ----------------
__global__ __launch_bounds__(NTHREADS, 2)
void gat_mma_kernel(float* __restrict__ out)
{
    extern __shared__ char smem[];
    const uint32_t sb = smem_u32(smem);

    const int tid  = threadIdx.x;
    const int wid  = tid >> 5;
    const int lane = tid & 31;

    const int batch = blockIdx.x >> 4;          // 32 batches x 16 mtiles
    const int mtile = blockIdx.x & 15;
    const int row0  = mtile * BM;
    const size_t xb = (size_t)batch * N_TOK * D_DIM;

    // ---- stage Q into smem, swizzled ----
    #pragma unroll
    for (int it = 0; it < 4; ++it) {
        int c   = tid + it * 256;               // 0..1023 chunks
        int row = c >> 3, cd = c & 7;
        uint32_t dst = SWZ_ADDR(0u, row, cd);
        *reinterpret_cast<uint4*>(smem + OFF_QH + dst) =
            *reinterpret_cast<const uint4*>(g_Xh + xb + (size_t)(row0 + row) * 64 + cd * 8);
    }

    // ---- K tile 0 preload via cp.async (key = tid>>2, chunks (tid&3)*2, +1) ----
    const int pk_key = tid >> 2;
    const int pk_cd  = (tid & 3) * 2;
    const uint32_t kst_dst0 = SWZ_ADDR(0u, pk_key, pk_cd);
    const uint32_t kst_dst1 = SWZ_ADDR(0u, pk_key, pk_cd + 1);
    {
        const size_t src = xb + (size_t)pk_key * 64 + pk_cd * 8;
        cp_async16(sb + OFF_K0 + kst_dst0, g_Xh + src);
        cp_async16(sb + OFF_K0 + kst_dst1, g_Xh + src + 8);
        cp_async_commit();
    }

    // per-warp fragment state
    float O[8][4];
    #pragma unroll
    for (int t = 0; t < 8; ++t)
        #pragma unroll
        for (int j = 0; j < 4; ++j) O[t][j] = 0.0f;
    float lA = 0.0f, lB = 0.0f;

    const int rowA = row0 + wid * 16 + (lane >> 2);   // global q-row of d0/d1
    const int qrow   = wid * 16 + (lane & 7) + ((lane >> 3) & 1) * 8;
    const int brow_b = ((lane >> 4) & 1) * 8 + (lane & 7);
    const int bchk_b = (lane >> 3) & 1;
    const int vrow_b = ((lane >> 3) & 1) * 8 + (lane & 7);

    cp_async_wait0();
    __syncthreads();   // Q smem + K tile 0 visible

    // ---- hoist Q fragments into registers (invariant across key tiles) ----
    uint32_t qh[4][4];
    #pragma unroll
    for (int kc = 0; kc < 4; ++kc) {
        const int qchunk = kc * 2 + (lane >> 4);
        ldm4(qh[kc], sb + OFF_QH + SWZ_ADDR(0u, qrow, qchunk));
    }

    for (int kt = 0; kt < NTILES; ++kt) {
        const uint32_t kbuf  = (kt & 1) ? OFF_K1 : OFF_K0;
        const uint32_t knext = (kt & 1) ? OFF_K0 : OFF_K1;

        // async prefetch of K(kt+1) into the idle buffer (overlaps compute)
        if (kt + 1 < NTILES) {
            const size_t src = xb + (size_t)((kt + 1) * BN + pk_key) * 64 + pk_cd * 8;
            cp_async16(sb + knext + kst_dst0, g_Xh + src);
            cp_async16(sb + knext + kst_dst1, g_Xh + src + 8);
            cp_async_commit();
        }

        // adjacency bits for my two rows, this tile's 64 keys
        uint2 mwA = *reinterpret_cast<const uint2*>(&g_adjm[(size_t)rowA * 64 + kt * 2]);
        uint2 mwB = *reinterpret_cast<const uint2*>(&g_adjm[(size_t)(rowA + 8) * 64 + kt * 2]);
        const uint64_t maskA = (uint64_t)mwA.x | ((uint64_t)mwA.y << 32);
        const uint64_t maskB = (uint64_t)mwB.x | ((uint64_t)mwB.y << 32);

        // ---- GEMM1: S = Qh * K^T  (single pass, Q from registers) ----
        float S[8][4];
        #pragma unroll
        for (int t = 0; t < 8; ++t)
            #pragma unroll
            for (int j = 0; j < 4; ++j) S[t][j] = 0.0f;

        #pragma unroll
        for (int kc = 0; kc < 4; ++kc) {
            #pragma unroll
            for (int g = 0; g < 4; ++g) {
                const int brow = g * 16 + brow_b;
                const int bchk = kc * 2 + bchk_b;
                uint32_t b[4];
                ldm4(b, sb + kbuf + SWZ_ADDR(0u, brow, bchk));
                mma16816(S[2*g],   qh[kc], b[0], b[1]);
                mma16816(S[2*g+1], qh[kc], b[2], b[3]);
            }
        }

        // ---- mask + shifted exp; pack P to f16 A-fragments directly ----
        uint32_t P[8][2];
        #pragma unroll
        for (int nt = 0; nt < 8; ++nt) {
            const int bit = nt * 8 + (lane & 3) * 2;
            float p0 = ((maskA >> bit) & 1ull)
                       ? ex2f(fmaf(S[nt][0], EXP2_SCALE, EXP2_SHIFT)) : 0.0f;
            float p1 = ((maskA >> (bit + 1)) & 1ull)
                       ? ex2f(fmaf(S[nt][1], EXP2_SCALE, EXP2_SHIFT)) : 0.0f;
            float p2 = ((maskB >> bit) & 1ull)
                       ? ex2f(fmaf(S[nt][2], EXP2_SCALE, EXP2_SHIFT)) : 0.0f;
            float p3 = ((maskB >> (bit + 1)) & 1ull)
                       ? ex2f(fmaf(S[nt][3], EXP2_SCALE, EXP2_SHIFT)) : 0.0f;
            lA += p0 + p1;
            lB += p2 + p3;
            P[nt][0] = pack_f16(p0, p1);
            P[nt][1] = pack_f16(p2, p3);
        }

        // ---- GEMM2: O += P * V  (single pass; V = K buffer via trans) ----
        #pragma unroll
        for (int u = 0; u < 4; ++u) {
            uint32_t a[4] = { P[2*u][0], P[2*u][1], P[2*u+1][0], P[2*u+1][1] };
            const int vrow = u * 16 + vrow_b;
            #pragma unroll
            for (int dd = 0; dd < 4; ++dd) {
                const int vchk = dd * 2 + (lane >> 4);
                uint32_t v[4];
                ldm4t(v, sb + kbuf + SWZ_ADDR(0u, vrow, vchk));
                mma16816(O[2*dd],   a, v[0], v[1]);
                mma16816(O[2*dd+1], a, v[2], v[3]);
            }
        }

        // drain the prefetch and publish buffer swap
        if (kt + 1 < NTILES) {
            cp_async_wait0();
            __syncthreads();
        }
    }

    // ---- epilogue: reduce l over quad, normalize, store ----
    lA += __shfl_xor_sync(0xffffffffu, lA, 1);
    lA += __shfl_xor_sync(0xffffffffu, lA, 2);
    lB += __shfl_xor_sync(0xffffffffu, lB, 1);
    lB += __shfl_xor_sync(0xffffffffu, lB, 2);
    const float invA = 1.0f / lA;
    const float invB = 1.0f / lB;

    float* poA = out + ((size_t)batch * N_TOK + rowA) * 64 + (lane & 3) * 2;
    float* poB = poA + 8 * 64;
    #pragma unroll
    for (int dt = 0; dt < 8; ++dt) {
        *reinterpret_cast<float2*>(poA + dt * 8) =
            make_float2(O[dt][0] * invA, O[dt][1] * invA);
        *reinterpret_cast<float2*>(poB + dt * 8) =
            make_float2(O[dt][2] * invB, O[dt][3] * invB);
    }
}

extern "C" void kernel_launch(void* const* d_in, const int* in_sizes, int n_in,
                              void* d_out, int out_size)
{
    const float* X   = (const float*)d_in[0];  // [32,2048,64] fp32
    const int*   adj = (const int*)d_in[1];    // [2048,2048] int32
    float*       out = (float*)d_out;

    convert_kernel<<<(N_BATCH * N_TOK * D_DIM / 4) / 256, 256>>>(X);
    adj_pack_kernel<<<(N_TOK * (N_TOK / 32)) / 256, 256>>>(adj);

    cudaFuncSetAttribute(gat_mma_kernel,
                         cudaFuncAttributeMaxDynamicSharedMemorySize, SMEM_BYTES);
    gat_mma_kernel<<<N_BATCH * (N_TOK / BM), NTHREADS, SMEM_BYTES>>>(out);
}